// round 17
// baseline (speedup 1.0000x reference)
#include <cuda_runtime.h>
#include <math.h>
#include <float.h>
#include <stdint.h>

// Problem constants (from reference): B=8, Z=4, X=32, Y=32, N=4096
#define NPTS   4096
#define NB     8
#define THREADS 512
#define NWARP  (THREADS / 32)
#define NITER  (NPTS / THREADS)   // 8 points per thread, register-resident
#define MAXKEEP 32
#define CUT2   4.0f               // sqrt(ss) < 2  <=>  ss < 4 (exact)

// Dynamic smem: 3 arrays of NPTS floats (pred pos, for pick broadcast only)
#define SMEM_BYTES (3 * NPTS * 4)

__device__ __forceinline__ float row_angle(float ax, float ay, float az,
                                           float bx, float by, float bz) {
    float na = sqrtf(ax * ax + ay * ay + az * az);
    float nb = sqrtf(bx * bx + by * by + bz * bz);
    float c = (ax * bx + ay * by + az * bz) / (na * nb);
    c = fminf(1.0f, fmaxf(-1.0f, c));
    return (acosf(c) / 3.14159265358979323846f) * 180.0f;
}

__global__ __launch_bounds__(THREADS, 1)
void mol_kernel(const float* __restrict__ pred,
                const float* __restrict__ targ,
                float* __restrict__ out) {
    extern __shared__ float sm[];
    float* s_p0 = sm;                   // [NPTS] pred pos normalized (broadcast src)
    float* s_p1 = s_p0 + NPTS;
    float* s_p2 = s_p1 + NPTS;

    __shared__ unsigned long long sMax[MAXKEEP + 1];  // packed pick per round
    __shared__ int   wCnt[NWARP];
    __shared__ int   kid[MAXKEEP];
    __shared__ float kRX[MAXKEEP], kRY[MAXKEEP], kRZ[MAXKEEP];
    __shared__ int   sMatch[MAXKEEP], sHit[MAXKEEP];
    __shared__ float sAngA[MAXKEEP];
    __shared__ int   sNTG;

    const int tid = threadIdx.x;
    const int lane = tid & 31;
    const int warp = tid >> 5;
    const int b = blockIdx.x;
    const float* P = pred + (long long)b * NPTS * 10;
    const float* T = targ + (long long)b * NPTS * 10;

    if (tid <= MAXKEEP) sMax[tid] = 0ull;
    if (tid < MAXKEEP) sMatch[tid] = 0x7fffffff;
    __syncthreads();   // init visible before any atomic

    // ---- Phase 1: strided float2 load (R8), EVERYTHING register-resident ----
    float cf[NITER], px[NITER], py[NITER], pz[NITER];     // pred
    float tc[NITER], t0[NITER], t1[NITER], t2[NITER];     // targ (real coords)
    int cnt = 0;
    unsigned long long pk = 0ull;
    #pragma unroll
    for (int j = 0; j < NITER; j++) {
        int n = tid + j * THREADS;
        const float* p = P + n * 10;
        const float* t = T + n * 10;
        // 40-byte pitch is 8-byte aligned for every n -> float2 loads legal
        float2 p01 = *(const float2*)p;
        float2 p23 = *(const float2*)(p + 2);
        float2 t01 = *(const float2*)t;
        float2 t23 = *(const float2*)(t + 2);
        float z = (float)(n >> 10), x = (float)((n >> 5) & 31), y = (float)(n & 31);
        float pc = p01.x;
        // sigmoid(c) > 0.5 <=> c > 0 (exact); /4, /32 exact pow2 mults
        cf[j] = (pc > 0.0f) ? pc : -FLT_MAX;
        px[j] = (p01.y + z) * 0.25f;
        py[j] = (p23.x + x) * 0.03125f;
        pz[j] = (p23.y + y) * 0.03125f;
        s_p0[n] = px[j]; s_p1[n] = py[j]; s_p2[n] = pz[j];
        tc[j] = t01.x;
        cnt += (t01.x > 0.5f) ? 1 : 0;
        t0[j] = ((t01.y + z) * 0.25f) * 25.0f;    // real coords (×25,25,4)
        t1[j] = ((t23.x + x) * 0.03125f) * 25.0f;
        t2[j] = ((t23.y + y) * 0.03125f) * 4.0f;
        // fold round-0 argmax: conf>0 => float bits order-preserving; tie -> lower n
        if (pc > 0.0f) {
            unsigned long long q = (((unsigned long long)__float_as_uint(pc)) << 32)
                                 | (unsigned long long)(NPTS - n);
            if (q > pk) pk = q;
        }
    }
    #pragma unroll
    for (int o = 16; o; o >>= 1) {
        unsigned long long q = __shfl_down_sync(0xffffffffu, pk, o);
        if (q > pk) pk = q;
        cnt += __shfl_down_sync(0xffffffffu, cnt, o);
    }
    if (lane == 0) {
        wCnt[warp] = cnt;
        if (pk) atomicMax(&sMax[0], pk);
    }
    __syncthreads();
    if (tid == 0) {
        int s = 0;
        for (int w = 0; w < NWARP; w++) s += wCnt[w];
        sNTG = s;
    }

    // ---- Phase 2: register-resident greedy NMS, ONE barrier per round ----
    int K = 0;
    for (int r = 0; r < MAXKEEP; r++) {
        unsigned long long mx = sMax[r];
        if (mx == 0ull) break;                 // uniform
        K = r + 1;
        int idx = NPTS - (int)(mx & 0xffffffffu);
        float c0 = s_p0[idx], c1 = s_p1[idx], c2 = s_p2[idx];   // LDS broadcast
        if (tid == 0) {
            kid[r] = idx;
            kRX[r] = c0 * 25.0f; kRY[r] = c1 * 25.0f; kRZ[r] = c2 * 4.0f;
        }
        unsigned long long nxt = 0ull;
        #pragma unroll
        for (int j = 0; j < NITER; j++) {
            if (cf[j] != -FLT_MAX) {
                float d0 = px[j] - c0, d1 = py[j] - c1, d2 = pz[j] - c2;
                float ss = (d0 * d0 + d1 * d1) + d2 * d2;
                if (ss < CUT2) {
                    cf[j] = -FLT_MAX;
                } else {
                    int n = tid + j * THREADS;
                    unsigned long long q =
                        (((unsigned long long)__float_as_uint(cf[j])) << 32)
                        | (unsigned long long)(NPTS - n);
                    if (q > nxt) nxt = q;
                }
            }
        }
        #pragma unroll
        for (int o = 16; o; o >>= 1) {
            unsigned long long q = __shfl_down_sync(0xffffffffu, nxt, o);
            if (q > nxt) nxt = q;
        }
        if (lane == 0 && nxt) atomicMax(&sMax[r + 1], nxt);
        __syncthreads();
    }

    // ---- Phase 3: single register pass matching (atomicMin on rare hits) ----
    #pragma unroll
    for (int j = 0; j < NITER; j++) {
        if (tc[j] > 0.5f) {
            int n = tid + j * THREADS;
            float a0 = t0[j], a1 = t1[j], a2 = t2[j];
            for (int k = 0; k < K; k++) {
                float d0 = a0 - kRX[k], d1 = a1 - kRY[k], d2 = a2 - kRZ[k];
                float ss = (d0 * d0 + d1 * d1) + d2 * d2;
                if (ss < CUT2) atomicMin(&sMatch[k], n);   // min n == first match
            }
        }
    }
    __syncthreads();

    // ---- Phase 4: K parallel angle computations (global reads, L2-hot) ----
    if (tid < K) {
        int mt = sMatch[tid];
        if (mt != 0x7fffffff) {
            const float* p = P + (long long)kid[tid] * 10 + 4;
            const float* t = T + (long long)mt * 10 + 4;
            float2 pa2 = *(const float2*)p;        // offsets 4..9 are 8B aligned
            float2 pb2 = *(const float2*)(p + 2);
            float2 pc2 = *(const float2*)(p + 4);
            float2 ta2 = *(const float2*)t;
            float2 tb2 = *(const float2*)(t + 2);
            float2 tc2 = *(const float2*)(t + 4);
            float ax = pa2.x, ay = pa2.y, az = pb2.x;
            float bx = pb2.y, by = pc2.x, bz = pc2.y;
            float cx = ay * bz - az * by;
            float cy = az * bx - ax * bz;
            float cz = ax * by - ay * bx;
            float tax = ta2.x, tay = ta2.y, taz = tb2.x;
            float tbx = tb2.y, tby = tc2.x, tbz = tc2.y;
            float tcx = tay * tbz - taz * tby;
            float tcy = taz * tbx - tax * tbz;
            float tcz = tax * tby - tay * tbx;
            sAngA[tid] = row_angle(ax, ay, az, tax, tay, taz)
                       + row_angle(bx, by, bz, tbx, tby, tbz)
                       + row_angle(cx, cy, cz, tcx, tcy, tcz);
            sHit[tid] = 1;
        } else {
            sAngA[tid] = 0.0f;
            sHit[tid] = 0;
        }
    }
    __syncthreads();

    // ---- Phase 5: deterministic epilogue ----
    if (tid == 0) {
        int tp = 0;
        float ang = 0.0f;
        for (int k = 0; k < K; k++) { tp += sHit[k]; ang += sAngA[k]; }
        float tpf = (float)tp;
        out[b * 3 + 0] = tpf;
        out[b * 3 + 1] = (float)K - tpf;
        out[b * 3 + 2] = (float)sNTG - tpf;
        out[3 * NB + b] = (tp > 0) ? (ang / (3.0f * tpf)) : 0.0f;
    }
}

extern "C" void kernel_launch(void* const* d_in, const int* in_sizes, int n_in,
                              void* d_out, int out_size) {
    const float* pred = (const float*)d_in[0];
    const float* targ = (const float*)d_in[1];
    float* out = (float*)d_out;
    cudaFuncSetAttribute(mol_kernel, cudaFuncAttributeMaxDynamicSharedMemorySize,
                         SMEM_BYTES);
    mol_kernel<<<NB, THREADS, SMEM_BYTES>>>(pred, targ, out);
}